// round 6
// baseline (speedup 1.0000x reference)
#include <cuda_runtime.h>
#include <cuda_bf16.h>
#include <math.h>

// Problem dims (fixed by the bench)
#define BB 131072
#define DD 256
#define KK 1024
#define LL 526

// -------- device scratch (no allocations allowed) --------
__device__ int   g_assign[BB];
__device__ int   g_count[KK];
__device__ int   g_offset[KK];
__device__ int   g_cursor[KK];
__device__ int   g_order[BB];
__device__ float g_c2[KK];

// ============================================================
// K1: centroid squared norms (one warp per centroid)
// ============================================================
__global__ void c2_kernel(const float* __restrict__ cent) {
    int k    = blockIdx.x * 8 + (threadIdx.x >> 5);
    int lane = threadIdx.x & 31;
    const float4* row = (const float4*)(cent + (size_t)k * DD);
    float s = 0.f;
    #pragma unroll
    for (int i = 0; i < 2; ++i) {
        float4 v = row[lane + 32 * i];
        s = fmaf(v.x, v.x, s); s = fmaf(v.y, v.y, s);
        s = fmaf(v.z, v.z, s); s = fmaf(v.w, v.w, s);
    }
    #pragma unroll
    for (int o = 16; o; o >>= 1) s += __shfl_xor_sync(0xffffffffu, s, o);
    if (!lane) g_c2[k] = s;
}

// ============================================================
// K2: fused distance-GEMM + argmin (assignment)
//  block: 256 threads, 128 points; loops over 16 tiles of 64 centroids
//  As[128][257] resident in smem (points read once from HBM)
//  Bs[2][32][64] double-buffered k-major (float4 reads)
// ============================================================
#define AS_STRIDE 257
#define AS_FLOATS (128 * AS_STRIDE)
#define BS_FLOATS (2 * 32 * 64)

__global__ void __launch_bounds__(256, 1)
assign_kernel(const float* __restrict__ pts, const float* __restrict__ cent,
              float* __restrict__ o_assign) {
    extern __shared__ float sm[];
    float* As = sm;                 // [128][257]
    float* Bs = sm + AS_FLOATS;     // [2][32][64]

    const int t   = threadIdx.x;
    const int blk = blockIdx.x;
    const int r   = t >> 4;   // 0..15 : row group (8 points each)
    const int c   = t & 15;   // 0..15 : col group (4 centroids each)

    // ---- fill As (row-major, matches gmem layout; coalesced float4 reads) ----
    {
        const float4* src = (const float4*)(pts + (size_t)blk * 128 * DD);
        #pragma unroll
        for (int it = 0; it < 32; ++it) {
            int f  = it * 256 + t;      // float4 index
            int p  = f >> 6;            // point within tile
            int d4 = f & 63;
            float4 v = src[f];
            float* dst = As + p * AS_STRIDE + d4 * 4;
            dst[0] = v.x; dst[1] = v.y; dst[2] = v.z; dst[3] = v.w;
        }
    }

    // B-tile loader: thread t loads 8 floats (2 float4 along d) of centroid n=t>>2
    const int bn  = t >> 2;      // 0..63
    const int bdq = t & 3;       // 0..3
    float4 pb0, pb1;
    {   // prefetch tile 0, chunk 0
        const float4* gp = (const float4*)(cent + (size_t)bn * DD + bdq * 8);
        pb0 = gp[0]; pb1 = gp[1];
        float* dst = Bs + (bdq * 8) * 64 + bn;
        dst[0 * 64] = pb0.x; dst[1 * 64] = pb0.y; dst[2 * 64] = pb0.z; dst[3 * 64] = pb0.w;
        dst[4 * 64] = pb1.x; dst[5 * 64] = pb1.y; dst[6 * 64] = pb1.z; dst[7 * 64] = pb1.w;
    }
    __syncthreads();

    float minv[8];
    int   mini[8];
    #pragma unroll
    for (int i = 0; i < 8; ++i) { minv[i] = 3.4e38f; mini[i] = 0; }

    const float* AsRow = As + (r * 8) * AS_STRIDE;
    int buf = 0;

    for (int tile = 0; tile < 16; ++tile) {
        float acc[8][4];
        #pragma unroll
        for (int i = 0; i < 8; ++i)
            #pragma unroll
            for (int j = 0; j < 4; ++j) acc[i][j] = 0.f;

        for (int ch = 0; ch < 8; ++ch) {
            int s = tile * 8 + ch + 1;
            bool havenext = (s < 128);
            if (havenext) {
                int nt = s >> 3, nc = s & 7;
                const float4* gp = (const float4*)(cent + (size_t)(nt * 64 + bn) * DD
                                                   + nc * 32 + bdq * 8);
                pb0 = gp[0]; pb1 = gp[1];
            }
            const float* Bp = Bs + buf * 2048;
            const float* Ap = AsRow + ch * 32;
            #pragma unroll
            for (int kk = 0; kk < 32; ++kk) {
                float4 bv = *(const float4*)(Bp + kk * 64 + c * 4);
                #pragma unroll
                for (int i = 0; i < 8; ++i) {
                    float av = Ap[i * AS_STRIDE + kk];
                    acc[i][0] = fmaf(av, bv.x, acc[i][0]);
                    acc[i][1] = fmaf(av, bv.y, acc[i][1]);
                    acc[i][2] = fmaf(av, bv.z, acc[i][2]);
                    acc[i][3] = fmaf(av, bv.w, acc[i][3]);
                }
            }
            if (havenext) {
                float* dst = Bs + (buf ^ 1) * 2048 + (bdq * 8) * 64 + bn;
                dst[0 * 64] = pb0.x; dst[1 * 64] = pb0.y; dst[2 * 64] = pb0.z; dst[3 * 64] = pb0.w;
                dst[4 * 64] = pb1.x; dst[5 * 64] = pb1.y; dst[6 * 64] = pb1.z; dst[7 * 64] = pb1.w;
            }
            __syncthreads();
            buf ^= 1;
        }

        // ---- epilogue: scores = c2 - 2*dot, argmin ----
        float c2v[4];
        #pragma unroll
        for (int j = 0; j < 4; ++j) c2v[j] = g_c2[tile * 64 + c * 4 + j];

        #pragma unroll
        for (int i = 0; i < 8; ++i) {
            float bvv = c2v[0] - 2.f * acc[i][0];
            int   bii = tile * 64 + c * 4;
            #pragma unroll
            for (int j = 1; j < 4; ++j) {
                float v = c2v[j] - 2.f * acc[i][j];
                if (v < bvv) { bvv = v; bii = tile * 64 + c * 4 + j; }
            }
            // reduce across the 16 column-threads (stays within half-warp)
            #pragma unroll
            for (int o = 1; o < 16; o <<= 1) {
                float ov = __shfl_xor_sync(0xffffffffu, bvv, o);
                int   oi = __shfl_xor_sync(0xffffffffu, bii, o);
                if (ov < bvv || (ov == bvv && oi < bii)) { bvv = ov; bii = oi; }
            }
            if (bvv < minv[i] || (bvv == minv[i] && bii < mini[i])) {
                minv[i] = bvv; mini[i] = bii;
            }
        }
    }

    if (c == 0) {
        #pragma unroll
        for (int i = 0; i < 8; ++i) {
            int m = blk * 128 + r * 8 + i;
            o_assign[m] = (float)mini[i];
            g_assign[m] = mini[i];
            atomicAdd(&g_count[mini[i]], 1);
        }
    }
}

// ============================================================
// K3: exclusive scan of cluster counts (single block) + new_n output
// ============================================================
__global__ void scan_kernel(float* __restrict__ o_nn) {
    __shared__ int sc[KK];
    int t = threadIdx.x;
    int v = g_count[t];
    o_nn[t] = (float)v;
    sc[t] = v;
    __syncthreads();
    for (int o = 1; o < KK; o <<= 1) {
        int add = (t >= o) ? sc[t - o] : 0;
        __syncthreads();
        sc[t] += add;
        __syncthreads();
    }
    int excl = sc[t] - v;
    g_offset[t] = excl;
    g_cursor[t] = excl;
}

// ============================================================
// K4: per-point (one warp per point): dist, dist_labels,
//     dispersion atomics, bucket scatter
// ============================================================
__global__ void __launch_bounds__(256)
point_kernel(const float* __restrict__ pts, const float* __restrict__ labels,
             const float* __restrict__ cent, const float* __restrict__ rl,
             float* __restrict__ o_dist, float* __restrict__ o_disp,
             float* __restrict__ o_dlab, float* __restrict__ o_displ) {
    int p    = blockIdx.x * 8 + (threadIdx.x >> 5);
    int lane = threadIdx.x & 31;
    int a    = g_assign[p];

    // squared distance to assigned centroid (direct form, as in reference)
    const float4* pr = (const float4*)(pts  + (size_t)p * DD);
    const float4* cr = (const float4*)(cent + (size_t)a * DD);
    float s = 0.f;
    #pragma unroll
    for (int i = 0; i < 2; ++i) {
        float4 x = pr[lane + 32 * i];
        float4 y = cr[lane + 32 * i];
        float dx = x.x - y.x, dy = x.y - y.y, dz = x.z - y.z, dw = x.w - y.w;
        s = fmaf(dx, dx, s); s = fmaf(dy, dy, s);
        s = fmaf(dz, dz, s); s = fmaf(dw, dw, s);
    }
    #pragma unroll
    for (int o = 16; o; o >>= 1) s += __shfl_xor_sync(0xffffffffu, s, o);

    // cosine distance to assigned cluster label profile
    const float2* lr = (const float2*)(labels + (size_t)p * LL);
    const float2* rr = (const float2*)(rl     + (size_t)a * LL);
    float nn = 0.f, dd = 0.f, n1 = 0.f;
    for (int i = lane; i < LL / 2; i += 32) {   // LL even (526) -> 263 float2
        float2 lv = lr[i];
        float2 rv = rr[i];
        nn = fmaf(lv.x, lv.x, nn); nn = fmaf(lv.y, lv.y, nn);
        dd = fmaf(lv.x, rv.x, dd); dd = fmaf(lv.y, rv.y, dd);
        n1 = fmaf(rv.x, rv.x, n1); n1 = fmaf(rv.y, rv.y, n1);
    }
    #pragma unroll
    for (int o = 16; o; o >>= 1) {
        nn += __shfl_xor_sync(0xffffffffu, nn, o);
        dd += __shfl_xor_sync(0xffffffffu, dd, o);
        n1 += __shfl_xor_sync(0xffffffffu, n1, o);
    }
    float dl = 1.f - dd / (sqrtf(nn) * sqrtf(n1) + 1e-8f);

    if (!lane) {
        o_dist[p] = s;
        o_dlab[p] = dl;
        atomicAdd(&o_disp[a],  s);
        atomicAdd(&o_displ[a], dl);
        int pos = atomicAdd(&g_cursor[a], 1);
        g_order[pos] = p;
    }
}

// ============================================================
// K5: per-cluster atomic-free segment sums (new_sum, new_labels)
//  one block per cluster; thread t owns columns t (D) and t, t+256, t+512 (L)
// ============================================================
__global__ void __launch_bounds__(256)
cluster_kernel(const float* __restrict__ pts, const float* __restrict__ labels,
               float* __restrict__ o_nsum, float* __restrict__ o_nlab) {
    int k    = blockIdx.x;
    int t    = threadIdx.x;
    int cnt  = g_count[k];
    int base = g_offset[k];

    float sd = 0.f, l0 = 0.f, l1 = 0.f, l2 = 0.f;
    int p = (cnt > 0) ? g_order[base] : 0;
    for (int m = 0; m < cnt; ++m) {
        int pn = (m + 1 < cnt) ? g_order[base + m + 1] : 0;
        const float* prow = pts    + (size_t)p * DD;
        const float* lrow = labels + (size_t)p * LL;
        sd += prow[t];
        l0 += lrow[t];
        l1 += lrow[t + 256];
        if (t < LL - 512) l2 += lrow[t + 512];
        p = pn;
    }
    o_nsum[(size_t)k * DD + t] = sd;
    o_nlab[(size_t)k * LL + t]       = l0;
    o_nlab[(size_t)k * LL + t + 256] = l1;
    if (t < LL - 512) o_nlab[(size_t)k * LL + t + 512] = l2;
}

// ============================================================
// launch
// ============================================================
extern "C" void kernel_launch(void* const* d_in, const int* in_sizes, int n_in,
                              void* d_out, int out_size) {
    const float* pts  = (const float*)d_in[0];
    const float* labs = (const float*)d_in[1];
    const float* cent = (const float*)d_in[2];
    const float* rl   = (const float*)d_in[3];
    float* out = (float*)d_out;

    // output layout (reference return order, flattened)
    float* o_assign = out;                                 // B
    float* o_dist   = o_assign + BB;                       // B
    float* o_disp   = o_dist   + BB;                       // K
    float* o_dlab   = o_disp   + KK;                       // B
    float* o_displ  = o_dlab   + BB;                       // K
    float* o_nsum   = o_displ  + KK;                       // K*D
    float* o_nn     = o_nsum   + (size_t)KK * DD;          // K
    float* o_nlab   = o_nn     + KK;                       // K*L

    void* p_count = nullptr;
    cudaGetSymbolAddress(&p_count, g_count);
    cudaMemsetAsync(p_count, 0, KK * sizeof(int));
    cudaMemsetAsync(o_disp,  0, KK * sizeof(float));
    cudaMemsetAsync(o_displ, 0, KK * sizeof(float));

    c2_kernel<<<KK / 8, 256>>>(cent);

    size_t smem = (size_t)(AS_FLOATS + BS_FLOATS) * sizeof(float);
    cudaFuncSetAttribute(assign_kernel,
                         cudaFuncAttributeMaxDynamicSharedMemorySize, (int)smem);
    assign_kernel<<<BB / 128, 256, smem>>>(pts, cent, o_assign);

    scan_kernel<<<1, KK>>>(o_nn);

    point_kernel<<<BB / 8, 256>>>(pts, labs, cent, rl,
                                  o_dist, o_disp, o_dlab, o_displ);

    cluster_kernel<<<KK, 256>>>(pts, labs, o_nsum, o_nlab);
}

// round 9
// speedup vs baseline: 1.3978x; 1.3978x over previous
#include <cuda_runtime.h>
#include <cuda_bf16.h>
#include <math.h>
#include <stdint.h>

// Problem dims (fixed by the bench)
#define BB 131072
#define DD 256
#define KK 1024
#define LL 526

// -------- device scratch (no allocations allowed) --------
__device__ int   g_assign[BB];
__device__ int   g_count[KK];
__device__ int   g_offset[KK];
__device__ int   g_cursor[KK];
__device__ int   g_order[BB];
__device__ float g_c2[KK];
__device__ __align__(16) __nv_bfloat16 g_cbf[KK * 512];   // [k][hi 256 | lo 256]

// ============================================================
// helpers
// ============================================================
__device__ __forceinline__ uint32_t smem_u32(const void* p) {
    uint32_t a;
    asm("{ .reg .u64 t; cvta.to.shared.u64 t, %1; cvt.u32.u64 %0, t; }" : "=r"(a) : "l"(p));
    return a;
}
__device__ __forceinline__ void ldsm4(uint32_t* r, uint32_t addr) {
    asm volatile("ldmatrix.sync.aligned.m8n8.x4.shared.b16 {%0,%1,%2,%3}, [%4];"
                 : "=r"(r[0]), "=r"(r[1]), "=r"(r[2]), "=r"(r[3]) : "r"(addr));
}
__device__ __forceinline__ void mma16816(float* c, const uint32_t* a, const uint32_t* b) {
    asm volatile("mma.sync.aligned.m16n8k16.row.col.f32.bf16.bf16.f32 "
                 "{%0,%1,%2,%3}, {%4,%5,%6,%7}, {%8,%9}, {%0,%1,%2,%3};"
                 : "+f"(c[0]), "+f"(c[1]), "+f"(c[2]), "+f"(c[3])
                 : "r"(a[0]), "r"(a[1]), "r"(a[2]), "r"(a[3]), "r"(b[0]), "r"(b[1]));
}
__device__ __forceinline__ void sts64(uint32_t addr, uint32_t a, uint32_t b) {
    asm volatile("st.shared.v2.b32 [%0], {%1,%2};" :: "r"(addr), "r"(a), "r"(b) : "memory");
}
__device__ __forceinline__ void sts128(uint32_t addr, uint4 v) {
    asm volatile("st.shared.v4.b32 [%0], {%1,%2,%3,%4};"
                 :: "r"(addr), "r"(v.x), "r"(v.y), "r"(v.z), "r"(v.w) : "memory");
}
__device__ __forceinline__ void sts32(uint32_t addr, uint32_t v) {
    asm volatile("st.shared.b32 [%0], %1;" :: "r"(addr), "r"(v) : "memory");
}
__device__ __forceinline__ float lds_f(uint32_t addr) {
    float v; asm volatile("ld.shared.f32 %0, [%1];" : "=f"(v) : "r"(addr)); return v;
}
__device__ __forceinline__ void lds64(uint32_t addr, uint32_t& a, uint32_t& b) {
    asm volatile("ld.shared.v2.b32 {%0,%1}, [%2];" : "=r"(a), "=r"(b) : "r"(addr));
}
__device__ __forceinline__ uint32_t pack_bf2(float a, float b) {
    __nv_bfloat162 h = __floats2bfloat162_rn(a, b);   // .x = a (low 16 bits)
    return *(uint32_t*)&h;
}

// ============================================================
// K1: centroid norms (fp32) + bf16 hi/lo split table
// ============================================================
__global__ void c2bf_kernel(const float* __restrict__ cent) {
    int k    = blockIdx.x * 8 + (threadIdx.x >> 5);
    int lane = threadIdx.x & 31;
    const float4* row = (const float4*)(cent + (size_t)k * DD);
    __nv_bfloat16* hi = g_cbf + (size_t)k * 512;
    __nv_bfloat16* lo = hi + 256;
    float s = 0.f;
    #pragma unroll
    for (int i = 0; i < 2; ++i) {
        int f4 = lane + 32 * i;
        float4 v = row[f4];
        s = fmaf(v.x, v.x, s); s = fmaf(v.y, v.y, s);
        s = fmaf(v.z, v.z, s); s = fmaf(v.w, v.w, s);
        int d = f4 * 4;
        __nv_bfloat16 h0 = __float2bfloat16(v.x), h1 = __float2bfloat16(v.y);
        __nv_bfloat16 h2 = __float2bfloat16(v.z), h3 = __float2bfloat16(v.w);
        hi[d] = h0; hi[d+1] = h1; hi[d+2] = h2; hi[d+3] = h3;
        lo[d]   = __float2bfloat16(v.x - __bfloat162float(h0));
        lo[d+1] = __float2bfloat16(v.y - __bfloat162float(h1));
        lo[d+2] = __float2bfloat16(v.z - __bfloat162float(h2));
        lo[d+3] = __float2bfloat16(v.w - __bfloat162float(h3));
    }
    #pragma unroll
    for (int o = 16; o; o >>= 1) s += __shfl_xor_sync(0xffffffffu, s, o);
    if (!lane) g_c2[k] = s;
}

// ============================================================
// K2: bf16 hi/lo mma.sync distance GEMM + argmin
//   CTA = 128 points. A[128][512] bf16 swizzled K-major rows (1024B stride).
//   16 N-tiles of 64 centroids. Warps: 4 (m) x 2 (n), warp tile m32 x n32.
//   Per k16-step: 8 ldmatrix.x4 + 24 mma (hi*hi, hi*lo, lo*hi).
// ============================================================
#define A_OFF   0
#define A_BYTES (128 * 1024)
#define B_OFF   A_BYTES
#define B_BYTES (64 * 1024)
#define SC2_OFF (B_OFF + B_BYTES)          // 64 floats
#define X2_OFF  (SC2_OFF + 256)            // 128 floats
#define RED_OFF (X2_OFF + 512)             // 128 rows x 2 slots x 8B
#define SMEM_REQ (RED_OFF + 2048)

__global__ void __launch_bounds__(256, 1)
assign_kernel(const float* __restrict__ pts,
              float* __restrict__ o_assign, float* __restrict__ o_dist,
              float* __restrict__ o_disp) {
    extern __shared__ char smraw[];
    const uint32_t smb = smem_u32(smraw);
    const uint32_t smA = smb + A_OFF;
    const uint32_t smB = smb + B_OFF;
    const uint32_t smC2 = smb + SC2_OFF;
    const uint32_t smX2 = smb + X2_OFF;
    const uint32_t smRD = smb + RED_OFF;

    const int t    = threadIdx.x;
    const int wid  = t >> 5;
    const int lane = t & 31;
    const int blk  = blockIdx.x;

    // ---- A fill: fp32 -> bf16 hi/lo, swizzled; also x2 per point ----
    {
        const float4* src = (const float4*)(pts + (size_t)blk * 128 * DD);
        #pragma unroll
        for (int it = 0; it < 16; ++it) {
            int r = it * 8 + wid;
            uint32_t rowb = smA + r * 1024;
            uint32_t x = (uint32_t)((r & 7) << 4);
            float x2 = 0.f;
            #pragma unroll
            for (int h = 0; h < 2; ++h) {
                int f4 = h * 32 + lane;
                float4 v = src[r * 64 + f4];
                x2 = fmaf(v.x, v.x, x2); x2 = fmaf(v.y, v.y, x2);
                x2 = fmaf(v.z, v.z, x2); x2 = fmaf(v.w, v.w, x2);
                __nv_bfloat16 h0 = __float2bfloat16(v.x), h1 = __float2bfloat16(v.y);
                __nv_bfloat16 h2 = __float2bfloat16(v.z), h3 = __float2bfloat16(v.w);
                uint32_t hiA, hiB;
                { __nv_bfloat162 p(h0, h1); hiA = *(uint32_t*)&p; }
                { __nv_bfloat162 p(h2, h3); hiB = *(uint32_t*)&p; }
                uint32_t loA = pack_bf2(v.x - __bfloat162float(h0),
                                        v.y - __bfloat162float(h1));
                uint32_t loB = pack_bf2(v.z - __bfloat162float(h2),
                                        v.w - __bfloat162float(h3));
                uint32_t kb = (uint32_t)(f4 * 8);            // hi byte offset
                sts64(rowb + (kb ^ x), hiA, hiB);
                sts64(rowb + ((512 + kb) ^ x), loA, loB);
            }
            #pragma unroll
            for (int o = 16; o; o >>= 1) x2 += __shfl_xor_sync(0xffffffffu, x2, o);
            if (!lane) sts32(smX2 + r * 4, __float_as_uint(x2));
        }
    }

    // warp tiling: 4 m-groups x 2 n-groups
    const int wm = wid & 3;            // m0 = wm*32
    const int wn = wid >> 2;           // n0 = wn*32
    const int m0 = wm * 32;
    const int n0 = wn * 32;

    // ldmatrix lane addressing (loop-invariant parts)
    const int ar  = m0 + (lane & 15);
    const uint32_t aAdr = smA + ar * 1024;
    const uint32_t ax   = (uint32_t)((ar & 7) << 4);
    const uint32_t acA  = (uint32_t)((lane >> 4) << 4);
    const int br  = n0 + ((lane & 7) + ((lane >> 4) << 3));
    const uint32_t bAdr = smB + br * 1024;
    const uint32_t bx   = (uint32_t)((br & 7) << 4);
    const uint32_t bcA  = (uint32_t)(((lane >> 3) & 1) << 4);

    float acc[2][4][4];
    #pragma unroll
    for (int i = 0; i < 2; ++i)
        #pragma unroll
        for (int j = 0; j < 4; ++j)
            #pragma unroll
            for (int e = 0; e < 4; ++e) acc[i][j][e] = 0.f;

    float minv[2][2];
    int   mini[2][2];
    #pragma unroll
    for (int i = 0; i < 2; ++i)
        #pragma unroll
        for (int j = 0; j < 2; ++j) { minv[i][j] = 3.4e38f; mini[i][j] = 0; }

    for (int tile = 0; tile < 16; ++tile) {
        __syncthreads();   // epilogue of prev tile done before overwriting B/sc2
        // ---- B fill: 64 centroids x 1024B from g_cbf (hi|lo contiguous) ----
        {
            const uint4* src = (const uint4*)g_cbf + (size_t)(tile * 64) * 64;
            #pragma unroll
            for (int i = 0; i < 16; ++i) {
                int idx = i * 256 + t;
                int n  = idx >> 6;
                int ch = idx & 63;
                uint4 v = src[idx];
                sts128(smB + n * 1024 + (((uint32_t)(ch * 16)) ^ ((n & 7) << 4)), v);
            }
            if (t < 64) sts32(smC2 + t * 4, __float_as_uint(g_c2[tile * 64 + t]));
        }
        __syncthreads();

        // ---- mainloop: 16 k-steps of 16 ----
        #pragma unroll 2
        for (int ks = 0; ks < 16; ++ks) {
            uint32_t khb = (uint32_t)(ks * 32);
            uint32_t ah[2][4], al[2][4], bh[2][4], bl[2][4];
            ldsm4(ah[0], aAdr +         ((khb + acA) ^ ax));
            ldsm4(ah[1], aAdr + 16384 + ((khb + acA) ^ ax));
            ldsm4(al[0], aAdr +         ((512 + khb + acA) ^ ax));
            ldsm4(al[1], aAdr + 16384 + ((512 + khb + acA) ^ ax));
            ldsm4(bh[0], bAdr +         ((khb + bcA) ^ bx));
            ldsm4(bh[1], bAdr + 16384 + ((khb + bcA) ^ bx));
            ldsm4(bl[0], bAdr +         ((512 + khb + bcA) ^ bx));
            ldsm4(bl[1], bAdr + 16384 + ((512 + khb + bcA) ^ bx));
            // hi*hi
            #pragma unroll
            for (int mf = 0; mf < 2; ++mf)
                #pragma unroll
                for (int nf = 0; nf < 4; ++nf)
                    mma16816(acc[mf][nf], ah[mf], &bh[nf >> 1][(nf & 1) * 2]);
            // hi_a * lo_b
            #pragma unroll
            for (int mf = 0; mf < 2; ++mf)
                #pragma unroll
                for (int nf = 0; nf < 4; ++nf)
                    mma16816(acc[mf][nf], ah[mf], &bl[nf >> 1][(nf & 1) * 2]);
            // lo_a * hi_b
            #pragma unroll
            for (int mf = 0; mf < 2; ++mf)
                #pragma unroll
                for (int nf = 0; nf < 4; ++nf)
                    mma16816(acc[mf][nf], al[mf], &bh[nf >> 1][(nf & 1) * 2]);
        }

        // ---- epilogue: scores = c2 - 2*dot, running argmin; reset acc ----
        #pragma unroll
        for (int mf = 0; mf < 2; ++mf)
            #pragma unroll
            for (int nf = 0; nf < 4; ++nf) {
                int colb = n0 + nf * 8 + (lane & 3) * 2;   // within tile (0..63)
                float c20 = lds_f(smC2 + colb * 4);
                float c21 = lds_f(smC2 + colb * 4 + 4);
                int g0 = tile * 64 + colb;
                float* c = acc[mf][nf];
                float v0 = c20 - 2.f * c[0];
                float v1 = c21 - 2.f * c[1];
                float v2 = c20 - 2.f * c[2];
                float v3 = c21 - 2.f * c[3];
                if (v0 < minv[mf][0] || (v0 == minv[mf][0] && g0     < mini[mf][0])) { minv[mf][0] = v0; mini[mf][0] = g0; }
                if (v1 < minv[mf][0] || (v1 == minv[mf][0] && g0 + 1 < mini[mf][0])) { minv[mf][0] = v1; mini[mf][0] = g0 + 1; }
                if (v2 < minv[mf][1] || (v2 == minv[mf][1] && g0     < mini[mf][1])) { minv[mf][1] = v2; mini[mf][1] = g0; }
                if (v3 < minv[mf][1] || (v3 == minv[mf][1] && g0 + 1 < mini[mf][1])) { minv[mf][1] = v3; mini[mf][1] = g0 + 1; }
                c[0] = 0.f; c[1] = 0.f; c[2] = 0.f; c[3] = 0.f;
            }
    }

    // ---- reduce argmin: intra-warp over lane&3, then cross n-warp via smem ----
    #pragma unroll
    for (int off = 1; off < 4; off <<= 1) {
        #pragma unroll
        for (int mf = 0; mf < 2; ++mf)
            #pragma unroll
            for (int rh = 0; rh < 2; ++rh) {
                float ov = __shfl_xor_sync(0xffffffffu, minv[mf][rh], off);
                int   oi = __shfl_xor_sync(0xffffffffu, mini[mf][rh], off);
                if (ov < minv[mf][rh] || (ov == minv[mf][rh] && oi < mini[mf][rh])) {
                    minv[mf][rh] = ov; mini[mf][rh] = oi;
                }
            }
    }
    if ((lane & 3) == 0) {
        #pragma unroll
        for (int mf = 0; mf < 2; ++mf)
            #pragma unroll
            for (int rh = 0; rh < 2; ++rh) {
                int row = m0 + mf * 16 + rh * 8 + (lane >> 2);
                sts64(smRD + (row * 2 + wn) * 8,
                      __float_as_uint(minv[mf][rh]), (uint32_t)mini[mf][rh]);
            }
    }
    __syncthreads();

    if (t < 128) {
        uint32_t v0u, i0u, v1u, i1u;
        lds64(smRD + (t * 2 + 0) * 8, v0u, i0u);
        lds64(smRD + (t * 2 + 1) * 8, v1u, i1u);
        float v0 = __uint_as_float(v0u), v1 = __uint_as_float(v1u);
        int   i0 = (int)i0u,             i1 = (int)i1u;
        float bv = v0; int bi = i0;
        if (v1 < bv || (v1 == bv && i1 < bi)) { bv = v1; bi = i1; }

        int p = blk * 128 + t;
        o_assign[p] = (float)bi;
        g_assign[p] = bi;
        float dist = bv + lds_f(smX2 + t * 4);
        o_dist[p] = dist;
        atomicAdd(&o_disp[bi], dist);
        atomicAdd(&g_count[bi], 1);
    }
}

// ============================================================
// K3: exclusive scan of cluster counts (single block) + new_n output
// ============================================================
__global__ void scan_kernel(float* __restrict__ o_nn) {
    __shared__ int sc[KK];
    int t = threadIdx.x;
    int v = g_count[t];
    o_nn[t] = (float)v;
    sc[t] = v;
    __syncthreads();
    for (int o = 1; o < KK; o <<= 1) {
        int add = (t >= o) ? sc[t - o] : 0;
        __syncthreads();
        sc[t] += add;
        __syncthreads();
    }
    int excl = sc[t] - v;
    g_offset[t] = excl;
    g_cursor[t] = excl;
}

// ============================================================
// K4: per-point labels cosine + dispersion_labels + bucket scatter
// ============================================================
__global__ void __launch_bounds__(256)
label_kernel(const float* __restrict__ labels, const float* __restrict__ rl,
             float* __restrict__ o_dlab, float* __restrict__ o_displ) {
    int p    = blockIdx.x * 8 + (threadIdx.x >> 5);
    int lane = threadIdx.x & 31;
    int a    = g_assign[p];

    const float2* lr = (const float2*)(labels + (size_t)p * LL);
    const float2* rr = (const float2*)(rl     + (size_t)a * LL);
    float nn = 0.f, dd = 0.f, n1 = 0.f;
    for (int i = lane; i < LL / 2; i += 32) {
        float2 lv = lr[i];
        float2 rv = rr[i];
        nn = fmaf(lv.x, lv.x, nn); nn = fmaf(lv.y, lv.y, nn);
        dd = fmaf(lv.x, rv.x, dd); dd = fmaf(lv.y, rv.y, dd);
        n1 = fmaf(rv.x, rv.x, n1); n1 = fmaf(rv.y, rv.y, n1);
    }
    #pragma unroll
    for (int o = 16; o; o >>= 1) {
        nn += __shfl_xor_sync(0xffffffffu, nn, o);
        dd += __shfl_xor_sync(0xffffffffu, dd, o);
        n1 += __shfl_xor_sync(0xffffffffu, n1, o);
    }
    float dl = 1.f - dd / (sqrtf(nn) * sqrtf(n1) + 1e-8f);

    if (!lane) {
        o_dlab[p] = dl;
        atomicAdd(&o_displ[a], dl);
        int pos = atomicAdd(&g_cursor[a], 1);
        g_order[pos] = p;
    }
}

// ============================================================
// K5: per-cluster atomic-free segment sums (new_sum, new_labels)
// ============================================================
__global__ void __launch_bounds__(256)
cluster_kernel(const float* __restrict__ pts, const float* __restrict__ labels,
               float* __restrict__ o_nsum, float* __restrict__ o_nlab) {
    int k    = blockIdx.x;
    int t    = threadIdx.x;
    int cnt  = g_count[k];
    int base = g_offset[k];

    float sd = 0.f, l0 = 0.f, l1 = 0.f, l2 = 0.f;
    int p = (cnt > 0) ? g_order[base] : 0;
    for (int m = 0; m < cnt; ++m) {
        int pn = (m + 1 < cnt) ? g_order[base + m + 1] : 0;
        const float* prow = pts    + (size_t)p * DD;
        const float* lrow = labels + (size_t)p * LL;
        sd += prow[t];
        l0 += lrow[t];
        l1 += lrow[t + 256];
        if (t < LL - 512) l2 += lrow[t + 512];
        p = pn;
    }
    o_nsum[(size_t)k * DD + t] = sd;
    o_nlab[(size_t)k * LL + t]       = l0;
    o_nlab[(size_t)k * LL + t + 256] = l1;
    if (t < LL - 512) o_nlab[(size_t)k * LL + t + 512] = l2;
}

// ============================================================
// launch
// ============================================================
extern "C" void kernel_launch(void* const* d_in, const int* in_sizes, int n_in,
                              void* d_out, int out_size) {
    const float* pts  = (const float*)d_in[0];
    const float* labs = (const float*)d_in[1];
    const float* cent = (const float*)d_in[2];
    const float* rl   = (const float*)d_in[3];
    float* out = (float*)d_out;

    // output layout (reference return order, flattened)
    float* o_assign = out;                                 // B
    float* o_dist   = o_assign + BB;                       // B
    float* o_disp   = o_dist   + BB;                       // K
    float* o_dlab   = o_disp   + KK;                       // B
    float* o_displ  = o_dlab   + BB;                       // K
    float* o_nsum   = o_displ  + KK;                       // K*D
    float* o_nn     = o_nsum   + (size_t)KK * DD;          // K
    float* o_nlab   = o_nn     + KK;                       // K*L

    void* p_count = nullptr;
    cudaGetSymbolAddress(&p_count, g_count);
    cudaMemsetAsync(p_count, 0, KK * sizeof(int));
    cudaMemsetAsync(o_disp,  0, KK * sizeof(float));
    cudaMemsetAsync(o_displ, 0, KK * sizeof(float));

    c2bf_kernel<<<KK / 8, 256>>>(cent);

    cudaFuncSetAttribute(assign_kernel,
                         cudaFuncAttributeMaxDynamicSharedMemorySize, SMEM_REQ);
    assign_kernel<<<BB / 128, 256, SMEM_REQ>>>(pts, o_assign, o_dist, o_disp);

    scan_kernel<<<1, KK>>>(o_nn);

    label_kernel<<<BB / 8, 256>>>(labs, rl, o_dlab, o_displ);

    cluster_kernel<<<KK, 256>>>(pts, labs, o_nsum, o_nlab);
}